// round 13
// baseline (speedup 1.0000x reference)
#include <cuda_runtime.h>
#include <cuda_fp16.h>
#include <math.h>
#include <cstdint>

// ---------------- problem constants ----------------
#define BB 2
#define LL 2048
#define DD 2048
#define HV 32
#define HK 16
#define DK 128
#define DV 128
#define KCONV 4
#define KEY_DIM 2048
#define VAL_DIM 4096
#define CONV_DIM 8192
#define BL (BB * LL)          // 4096 rows
#define WSCALE 64.0f
#define INV_WSCALE (1.0f / 64.0f)

// ---------------- scratch (static device globals) ----------------
__device__ float g_mixed_raw[(size_t)BL * CONV_DIM];      // GEMM1 out
__device__ float g_vconv[(size_t)BL * VAL_DIM];           // conv+silu of v part
__device__ float g_z[(size_t)BL * VAL_DIM];
__device__ float g_qn[(size_t)BL * HK * DK];
__device__ float g_kn[(size_t)BL * HK * DK];
__device__ float g_beta[(size_t)BL * HV];
__device__ float g_dec[(size_t)BL * HV];
__device__ float g_core[(size_t)BL * HV * DV];
// fp16 operands
__device__ __half g_hid_h[(size_t)BL * DD];
__device__ __half g_wqkvt_hi[(size_t)CONV_DIM * DD];
__device__ __half g_wqkvt_lo[(size_t)CONV_DIM * DD];
__device__ __half g_wzt_hi[(size_t)VAL_DIM * DD];
__device__ __half g_wzt_lo[(size_t)VAL_DIM * DD];
__device__ __half g_woutt_hi[(size_t)DD * VAL_DIM];
__device__ __half g_woutt_lo[(size_t)DD * VAL_DIM];
__device__ __half g_gh[(size_t)BL * VAL_DIM];

// ============================================================================
// PTX helpers (legal on plain sm_103 target)
// ============================================================================
__device__ __forceinline__ uint32_t smem_u32(const void* p) {
    uint32_t a;
    asm("{ .reg .u64 t; cvta.to.shared.u64 t, %1; cvt.u32.u64 %0, t; }"
        : "=r"(a) : "l"(p));
    return a;
}
__device__ __forceinline__ void cp_async16(uint32_t dst, const void* src) {
    asm volatile("cp.async.cg.shared.global [%0], [%1], 16;" :: "r"(dst), "l"(src));
}
__device__ __forceinline__ void cp_async4(uint32_t dst, const void* src) {
    asm volatile("cp.async.ca.shared.global [%0], [%1], 4;" :: "r"(dst), "l"(src));
}
#define CP_COMMIT() asm volatile("cp.async.commit_group;" ::: "memory")
#define CP_WAIT2()  asm volatile("cp.async.wait_group 2;" ::: "memory")
#define CP_WAIT3()  asm volatile("cp.async.wait_group 3;" ::: "memory")

__device__ __forceinline__ void ldmx4(uint32_t* r, uint32_t addr) {
    asm volatile("ldmatrix.sync.aligned.m8n8.x4.shared.b16 {%0,%1,%2,%3}, [%4];"
                 : "=r"(r[0]), "=r"(r[1]), "=r"(r[2]), "=r"(r[3]) : "r"(addr));
}
__device__ __forceinline__ void mma16816h(float* c, const uint32_t* a, const uint32_t* b) {
    asm volatile(
        "mma.sync.aligned.m16n8k16.row.col.f32.f16.f16.f32 "
        "{%0,%1,%2,%3}, {%4,%5,%6,%7}, {%8,%9}, {%0,%1,%2,%3};"
        : "+f"(c[0]), "+f"(c[1]), "+f"(c[2]), "+f"(c[3])
        : "r"(a[0]), "r"(a[1]), "r"(a[2]), "r"(a[3]), "r"(b[0]), "r"(b[1]));
}

// packed fp32x2 ops (FFMA2)
typedef unsigned long long ull;
__device__ __forceinline__ ull pk2(float lo, float hi) {
    ull r; asm("mov.b64 %0, {%1, %2};" : "=l"(r) : "f"(lo), "f"(hi)); return r;
}
__device__ __forceinline__ float2 upk2(ull v) {
    float2 f; asm("mov.b64 {%0, %1}, %2;" : "=f"(f.x), "=f"(f.y) : "l"(v)); return f;
}
__device__ __forceinline__ ull fma2_(ull a, ull b, ull c) {
    ull d; asm("fma.rn.f32x2 %0, %1, %2, %3;" : "=l"(d) : "l"(a), "l"(b), "l"(c)); return d;
}
__device__ __forceinline__ ull mul2_(ull a, ull b) {
    ull d; asm("mul.rn.f32x2 %0, %1, %2;" : "=l"(d) : "l"(a), "l"(b)); return d;
}

// ============================================================================
// prep: fp32 -> fp16 (A operand)
// ============================================================================
__global__ __launch_bounds__(256) void cvt16_kernel(
    const float* __restrict__ x, __half* __restrict__ out, size_t n4)
{
    size_t i = (size_t)blockIdx.x * blockDim.x + threadIdx.x;
    if (i >= n4) return;
    float4 v = reinterpret_cast<const float4*>(x)[i];
    __half2 h0 = __floats2half2_rn(v.x, v.y);
    __half2 h1 = __floats2half2_rn(v.z, v.w);
    reinterpret_cast<__half2*>(out)[i * 2 + 0] = h0;
    reinterpret_cast<__half2*>(out)[i * 2 + 1] = h1;
}

// ============================================================================
// prep: W[Kdim,Ndim] fp32 -> (W*64)^T hi/lo fp16 [Ndim,Kdim]
// ============================================================================
__global__ __launch_bounds__(256) void transpose_split_kernel(
    const float* __restrict__ W, __half* __restrict__ Thi,
    __half* __restrict__ Tlo, int Kdim, int Ndim)
{
    __shared__ float s[32][33];
    const int n0 = blockIdx.x * 32;
    const int k0 = blockIdx.y * 32;
    const int tx = threadIdx.x & 31;
    const int ty = threadIdx.x >> 5;
#pragma unroll
    for (int r = ty; r < 32; r += 8)
        s[r][tx] = W[(size_t)(k0 + r) * Ndim + n0 + tx];
    __syncthreads();
#pragma unroll
    for (int r = ty; r < 32; r += 8) {
        float x = s[tx][r] * WSCALE;
        __half h = __float2half_rn(x);
        Thi[(size_t)(n0 + r) * Kdim + k0 + tx] = h;
        Tlo[(size_t)(n0 + r) * Kdim + k0 + tx] = __float2half_rn(x - __half2float(h));
    }
}

// ============================================================================
// HMMA fp16 GEMM: C[M,N] = outscale * A[M,K] @ (Bhi [+ Blo])[N,K]^T
// TERMS=2: hi+lo compensated weights (GEMM1). TERMS=1: hi only (GEMM2/3).
// Block 256x128, BK=32, 16 warps (4m x 4n), warp tile 64x32,
// cp.async 4-stage pipeline, ldmatrix from 80B-padded smem rows.
// ============================================================================
#define GBK 32
#define ROWB 80
#define A_BYTES (256 * ROWB)
#define B_BYTES (128 * ROWB)
#define STAGE_BYTES (A_BYTES + 2 * B_BYTES)        // 40960
#define NSTAGE 4
#define GEMM_SMEM (NSTAGE * STAGE_BYTES)           // 163840

template<int TERMS>
__global__ void __launch_bounds__(512, 1) gemm_hmma_kernel(
    const __half* __restrict__ A,
    const __half* __restrict__ Bhi, const __half* __restrict__ Blo,
    float* __restrict__ C, int M, int N, int K, float outscale)
{
    extern __shared__ char smem[];
    const uint32_t sb = smem_u32(smem);
    const int tid  = threadIdx.x;
    const int wid  = tid >> 5;
    const int lane = tid & 31;
    const int warp_m = wid & 3;
    const int warp_n = wid >> 2;
    const int m0 = blockIdx.y * 256;
    const int n0 = blockIdx.x * 128;

    const __half* asrc  = A   + (size_t)m0 * K;
    const __half* bsrc[2] = { Bhi + (size_t)n0 * K,
                              (TERMS == 2) ? Blo + (size_t)n0 * K : Bhi + (size_t)n0 * K };

    const int NCHUNK = (TERMS == 2) ? 2048 : 1536;   // 16B chunks per stage

    auto load_stage = [&](int buf, int k0) {
        const uint32_t base = sb + buf * STAGE_BYTES;
#pragma unroll
        for (int i = 0; i < (TERMS == 2 ? 4 : 3); i++) {
            int c = tid + i * 512;
            if (c >= NCHUNK) break;
            if (c < 1024) {
                int row = c >> 2, col = c & 3;
                cp_async16(base + row * ROWB + col * 16,
                           asrc + (size_t)row * K + k0 + col * 8);
            } else {
                int d = c - 1024;
                int arr = d >> 9;
                int w = d & 511;
                int row = w >> 2, col = w & 3;
                cp_async16(base + A_BYTES + arr * B_BYTES + row * ROWB + col * 16,
                           bsrc[arr] + (size_t)row * K + k0 + col * 8);
            }
        }
    };

    float acc[4][4][4];
#pragma unroll
    for (int a = 0; a < 4; a++)
#pragma unroll
        for (int b = 0; b < 4; b++)
#pragma unroll
            for (int cc = 0; cc < 4; cc++) acc[a][b][cc] = 0.f;

    const int NIT = K / GBK;
    load_stage(0, 0);       CP_COMMIT();
    load_stage(1, GBK);     CP_COMMIT();
    load_stage(2, 2 * GBK); CP_COMMIT();

    const int a_row_l = (lane & 15);
    const int a_kadd  = (lane >> 4) << 3;
    const int b_nadd  = (lane & 7) + ((lane >> 4) << 3);
    const int b_kadd  = ((lane >> 3) & 1) << 3;

    for (int it = 0; it < NIT; ++it) {
        CP_WAIT2();
        __syncthreads();
        if (it + 3 < NIT) load_stage((it + 3) & (NSTAGE - 1), (it + 3) * GBK);
        CP_COMMIT();

        const uint32_t stg  = sb + (it & (NSTAGE - 1)) * STAGE_BYTES;
        const uint32_t ab   = stg;
        const uint32_t bhib = stg + A_BYTES;
        const uint32_t blob = stg + A_BYTES + B_BYTES;

#pragma unroll
        for (int ks = 0; ks < 2; ks++) {
            const int k0 = ks * 16;
            uint32_t ahf[4][4];
            const uint32_t aoff = (uint32_t)((warp_m * 64 + a_row_l) * ROWB + (k0 + a_kadd) * 2);
#pragma unroll
            for (int mt = 0; mt < 4; mt++)
                ldmx4(ahf[mt], ab + aoff + mt * 16 * ROWB);

            uint32_t bhf[2][4], blf[2][4];
            const uint32_t boff = (uint32_t)((warp_n * 32 + b_nadd) * ROWB + (k0 + b_kadd) * 2);
#pragma unroll
            for (int bt = 0; bt < 2; bt++) {
                ldmx4(bhf[bt], bhib + boff + bt * 16 * ROWB);
                if (TERMS == 2) ldmx4(blf[bt], blob + boff + bt * 16 * ROWB);
            }
#pragma unroll
            for (int mt = 0; mt < 4; mt++) {
#pragma unroll
                for (int nt = 0; nt < 4; nt++) {
                    const uint32_t* bh = &bhf[nt >> 1][(nt & 1) * 2];
                    float* c = acc[mt][nt];
                    mma16816h(c, ahf[mt], bh);
                    if (TERMS == 2) {
                        const uint32_t* bl = &blf[nt >> 1][(nt & 1) * 2];
                        mma16816h(c, ahf[mt], bl);
                    }
                }
            }
        }
    }

    const int mrow = lane >> 2;
    const int ncol = (lane & 3) * 2;
#pragma unroll
    for (int mt = 0; mt < 4; mt++) {
#pragma unroll
        for (int nt = 0; nt < 4; nt++) {
            const int m = m0 + warp_m * 64 + mt * 16 + mrow;
            const int n = n0 + warp_n * 32 + nt * 8 + ncol;
            *reinterpret_cast<float2*>(C + (size_t)m * N + n) =
                make_float2(acc[mt][nt][0] * outscale, acc[mt][nt][1] * outscale);
            *reinterpret_cast<float2*>(C + (size_t)(m + 8) * N + n) =
                make_float2(acc[mt][nt][2] * outscale, acc[mt][nt][3] * outscale);
        }
    }
}

// ============================================================================
// b/a projection + beta/decay — R9 version (known-good)
// ============================================================================
__global__ __launch_bounds__(128) void ba_kernel(
    const float* __restrict__ hidden,
    const float* __restrict__ Wb, const float* __restrict__ Wa,
    const float* __restrict__ dt_bias, const float* __restrict__ A_log,
    float* __restrict__ beta, float* __restrict__ dec)
{
    __shared__ float h_sh[DD];
    __shared__ float partial[128];
    const size_t bl = blockIdx.x;
    const int t = threadIdx.x;
    const float* hrow = hidden + bl * DD;
    for (int i = t; i < DD; i += 128) h_sh[i] = hrow[i];
    __syncthreads();

    const int col  = t & 63;
    const int part = t >> 6;
    const float* W = (col < 32) ? Wb : Wa;
    const int cc = col & 31;
    float acc = 0.f;
    const int d0 = part * (DD / 2);
#pragma unroll 8
    for (int d = d0; d < d0 + DD / 2; d++) acc = fmaf(h_sh[d], W[d * HV + cc], acc);
    partial[t] = acc;
    __syncthreads();
    if (t < 64) {
        float v = partial[t] + partial[t + 64];
        if (col < 32) {
            beta[bl * HV + cc] = 1.f / (1.f + expf(-v));
        } else {
            float x = v + dt_bias[cc];
            float sp = (x > 20.f) ? x : log1pf(expf(x));
            dec[bl * HV + cc] = expf(-expf(A_log[cc]) * sp);
        }
    }
}

// ============================================================================
// Tiled conv+SiLU+l2norm for q,k — 8 l's per block (known-good R12)
// ============================================================================
#define CTL 8
__global__ __launch_bounds__(256) void convqk_kernel(
    const float* __restrict__ raw, const float* __restrict__ w,
    float* __restrict__ qn, float* __restrict__ kn)
{
    __shared__ float taps[CTL + 3][256];
    __shared__ float red[CTL][8];

    const int tile = blockIdx.x;
    const int hk   = blockIdx.y;
    const int b    = tile / (LL / CTL);
    const int l0   = (tile % (LL / CTL)) * CTL;
    const int t = threadIdx.x;
    const bool isk = t >= 128;
    const int d = t & 127;
    const int wid = t >> 5;
    const int ch = (isk ? KEY_DIM : 0) + hk * DK + d;

    for (int i = t; i < (CTL + 3) * 256; i += 256) {
        const int r = i >> 8;
        const int c = i & 255;
        const int gl = l0 + r - 3;
        const int cch = ((c < 128) ? 0 : KEY_DIM) + hk * DK + (c & 127);
        taps[r][c] = (gl >= 0)
            ? raw[((size_t)b * LL + gl) * CONV_DIM + cch] : 0.f;
    }
    __syncthreads();

    const float4 wv = reinterpret_cast<const float4*>(w)[ch];
    float xr[CTL];
#pragma unroll
    for (int l = 0; l < CTL; l++) {
        float acc = taps[l + 3][t] * wv.w;
        acc = fmaf(taps[l + 2][t], wv.z, acc);
        acc = fmaf(taps[l + 1][t], wv.y, acc);
        acc = fmaf(taps[l + 0][t], wv.x, acc);
        xr[l] = acc / (1.f + expf(-acc));
        float ss = xr[l] * xr[l];
#pragma unroll
        for (int o = 16; o > 0; o >>= 1) ss += __shfl_down_sync(0xffffffffu, ss, o);
        if ((t & 31) == 0) red[l][wid] = ss;
    }
    __syncthreads();

#pragma unroll
    for (int l = 0; l < CTL; l++) {
        float tot = isk ? (red[l][4] + red[l][5] + red[l][6] + red[l][7])
                        : (red[l][0] + red[l][1] + red[l][2] + red[l][3]);
        float inv = rsqrtf(tot + 1e-6f);
        if (!isk) inv *= 0.08838834764831845f;
        const size_t orow = ((size_t)b * LL + l0 + l) * HK + hk;
        (isk ? kn : qn)[orow * DK + d] = xr[l] * inv;
    }
}

// ============================================================================
// Tiled conv+SiLU for v -> compact [BL, VAL_DIM] (known-good R12)
// ============================================================================
__global__ __launch_bounds__(256) void convv_kernel(
    const float* __restrict__ raw, const float* __restrict__ w,
    float* __restrict__ vconv)
{
    __shared__ float taps[CTL + 3][256];

    const int tile = blockIdx.x;
    const int cb   = blockIdx.y;
    const int b    = tile / (LL / CTL);
    const int l0   = (tile % (LL / CTL)) * CTL;
    const int t = threadIdx.x;
    const int ch = 2 * KEY_DIM + cb * 256 + t;
    const int vch = cb * 256 + t;

    for (int i = t; i < (CTL + 3) * 256; i += 256) {
        const int r = i >> 8;
        const int c = i & 255;
        const int gl = l0 + r - 3;
        taps[r][c] = (gl >= 0)
            ? raw[((size_t)b * LL + gl) * CONV_DIM + 2 * KEY_DIM + cb * 256 + c] : 0.f;
    }
    __syncthreads();

    const float4 wv = reinterpret_cast<const float4*>(w)[ch];
#pragma unroll
    for (int l = 0; l < CTL; l++) {
        float acc = taps[l + 3][t] * wv.w;
        acc = fmaf(taps[l + 2][t], wv.z, acc);
        acc = fmaf(taps[l + 1][t], wv.y, acc);
        acc = fmaf(taps[l + 0][t], wv.x, acc);
        vconv[((size_t)b * LL + l0 + l) * VAL_DIM + vch] =
            acc / (1.f + expf(-acc));
    }
}

// ============================================================================
// Gated delta-rule recurrence — R9 version (known-good)
// ============================================================================
#define DNBUF 4
__global__ __launch_bounds__(256) void delta_kernel(
    const float* __restrict__ qn, const float* __restrict__ kn,
    const float* __restrict__ vconv,
    const float* __restrict__ beta, const float* __restrict__ dec,
    float* __restrict__ core)
{
    const int c = blockIdx.x;
    const int b  = c >> 6;
    const int rm = c & 63;
    const int h  = rm >> 1;
    const int vh = rm & 1;
    const int hk = h >> 1;
    const int tid = threadIdx.x;
    const int vl = tid & 63;
    const int kh = tid >> 6;
    const int v  = vh * 64 + vl;

    __shared__ float ksh[DNBUF][128], qsh[DNBUF][128], vsh[DNBUF][64];
    __shared__ float scl[DNBUF][2];
    __shared__ float kvp[256], op[256];

    const uint32_t ksh_a = smem_u32(&ksh[0][0]);
    const uint32_t qsh_a = smem_u32(&qsh[0][0]);
    const uint32_t vsh_a = smem_u32(&vsh[0][0]);
    const uint32_t scl_a = smem_u32(&scl[0][0]);

    auto issue = [&](int l) {
        const int s = l & (DNBUF - 1);
        const size_t base = (size_t)b * LL + l;
        if (tid < 128)
            cp_async4(ksh_a + (s * 128 + tid) * 4,
                      kn + (base * HK + hk) * DK + tid);
        else
            cp_async4(qsh_a + (s * 128 + tid - 128) * 4,
                      qn + (base * HK + hk) * DK + (tid - 128));
        if (tid < 64)
            cp_async4(vsh_a + (s * 64 + tid) * 4,
                      vconv + base * VAL_DIM + (size_t)h * DV + vh * 64 + tid);
        else if (tid == 64)
            cp_async4(scl_a + (s * 2 + 0) * 4, dec + base * HV + h);
        else if (tid == 65)
            cp_async4(scl_a + (s * 2 + 1) * 4, beta + base * HV + h);
    };

    ull s2[16];
#pragma unroll
    for (int i = 0; i < 16; i++) s2[i] = 0ull;

    issue(0); CP_COMMIT();
    issue(1); CP_COMMIT();
    issue(2); CP_COMMIT();

    for (int l = 0; l < LL; l++) {
        const int s = l & (DNBUF - 1);
        if (l + 3 < LL) issue(l + 3);
        CP_COMMIT();
        CP_WAIT3();
        __syncthreads();

        const float dc = scl[s][0];
        const float bt = scl[s][1];
        const float2* kb2 = reinterpret_cast<const float2*>(&ksh[s][kh * 32]);
        const float2* qb2 = reinterpret_cast<const float2*>(&qsh[s][kh * 32]);

        const ull dc2 = pk2(dc, dc);
        ull kp[16];
        ull kv2 = 0ull;
#pragma unroll
        for (int j = 0; j < 16; j++) {
            float2 kf = kb2[j];
            kp[j] = pk2(kf.x, kf.y);
            s2[j] = mul2_(s2[j], dc2);
            kv2 = fma2_(kp[j], s2[j], kv2);
        }
        float2 kvf = upk2(kv2);
        kvp[kh * 64 + vl] = kvf.x + kvf.y;
        __syncthreads();

        const float kvs = kvp[vl] + kvp[64 + vl] + kvp[128 + vl] + kvp[192 + vl];
        const float delta = (vsh[s][vl] - kvs) * bt;
        const ull d2 = pk2(delta, delta);
        ull o2 = 0ull;
#pragma unroll
        for (int j = 0; j < 16; j++) {
            s2[j] = fma2_(kp[j], d2, s2[j]);
            float2 qf = qb2[j];
            o2 = fma2_(pk2(qf.x, qf.y), s2[j], o2);
        }
        float2 of = upk2(o2);
        op[kh * 64 + vl] = of.x + of.y;
        __syncthreads();

        if (kh == 0)
            core[((size_t)(b * LL + l) * HV + h) * DV + v] =
                op[vl] + op[64 + vl] + op[128 + vl] + op[192 + vl];
    }
}

// ============================================================================
// Gated RMSNorm -> fp16 (GEMM3 A operand)
// ============================================================================
__global__ __launch_bounds__(128) void gatednorm_kernel(
    const float* __restrict__ z, const float* __restrict__ norm_w,
    const float* __restrict__ core, __half* __restrict__ gh)
{
    const size_t row = blockIdx.x;
    const int t = threadIdx.x;
    const float zz = z[row * DV + t];
    const float cval = core[row * DV + t];
    const float g = cval * (zz / (1.f + expf(-zz)));

    __shared__ float red[4];
    float ss = g * g;
#pragma unroll
    for (int o = 16; o > 0; o >>= 1) ss += __shfl_down_sync(0xffffffffu, ss, o);
    if ((t & 31) == 0) red[t >> 5] = ss;
    __syncthreads();
    const float tot = red[0] + red[1] + red[2] + red[3];
    const float inv = rsqrtf(tot * (1.f / DV) + 1e-6f);
    gh[row * DV + t] = __float2half_rn(g * inv * norm_w[t]);
}

// ============================================================================
// launch
// ============================================================================
extern "C" void kernel_launch(void* const* d_in, const int* in_sizes, int n_in,
                              void* d_out, int out_size)
{
    const float* hidden  = (const float*)d_in[0];
    const float* W_qkv   = (const float*)d_in[1];
    const float* W_z     = (const float*)d_in[2];
    const float* W_b     = (const float*)d_in[3];
    const float* W_a     = (const float*)d_in[4];
    const float* conv_w  = (const float*)d_in[5];
    const float* dt_bias = (const float*)d_in[6];
    const float* A_log   = (const float*)d_in[7];
    const float* norm_w  = (const float*)d_in[8];
    const float* W_out   = (const float*)d_in[9];
    float* out = (float*)d_out;

    float *mixed_raw, *vconv, *zbuf, *qn, *kn, *betab, *decb, *core;
    __half *hid_h, *wqkvt_hi, *wqkvt_lo, *wzt_hi, *wzt_lo, *woutt_hi, *woutt_lo, *gh;
    cudaGetSymbolAddress((void**)&mixed_raw, g_mixed_raw);
    cudaGetSymbolAddress((void**)&vconv,     g_vconv);
    cudaGetSymbolAddress((void**)&zbuf,      g_z);
    cudaGetSymbolAddress((void**)&qn,        g_qn);
    cudaGetSymbolAddress((void**)&kn,        g_kn);
    cudaGetSymbolAddress((void**)&betab,     g_beta);
    cudaGetSymbolAddress((void**)&decb,      g_dec);
    cudaGetSymbolAddress((void**)&core,      g_core);
    cudaGetSymbolAddress((void**)&hid_h,     g_hid_h);
    cudaGetSymbolAddress((void**)&wqkvt_hi,  g_wqkvt_hi);
    cudaGetSymbolAddress((void**)&wqkvt_lo,  g_wqkvt_lo);
    cudaGetSymbolAddress((void**)&wzt_hi,    g_wzt_hi);
    cudaGetSymbolAddress((void**)&wzt_lo,    g_wzt_lo);
    cudaGetSymbolAddress((void**)&woutt_hi,  g_woutt_hi);
    cudaGetSymbolAddress((void**)&woutt_lo,  g_woutt_lo);
    cudaGetSymbolAddress((void**)&gh,        g_gh);

    cudaFuncSetAttribute(gemm_hmma_kernel<2>,
                         cudaFuncAttributeMaxDynamicSharedMemorySize, GEMM_SMEM);
    cudaFuncSetAttribute(gemm_hmma_kernel<1>,
                         cudaFuncAttributeMaxDynamicSharedMemorySize, GEMM_SMEM);

    // ---- prep ----
    cvt16_kernel<<<(unsigned)(((size_t)BL * DD / 4 + 255) / 256), 256>>>(
        hidden, hid_h, (size_t)BL * DD / 4);
    transpose_split_kernel<<<dim3(CONV_DIM / 32, DD / 32), 256>>>(
        W_qkv, wqkvt_hi, wqkvt_lo, DD, CONV_DIM);
    transpose_split_kernel<<<dim3(VAL_DIM / 32, DD / 32), 256>>>(
        W_z, wzt_hi, wzt_lo, DD, VAL_DIM);
    transpose_split_kernel<<<dim3(DD / 32, VAL_DIM / 32), 256>>>(
        W_out, woutt_hi, woutt_lo, VAL_DIM, DD);

    // ---- GEMM1 (2-term, feeds recurrence): mixed_raw = hidden @ W_qkv ----
    gemm_hmma_kernel<2><<<dim3(CONV_DIM / 128, BL / 256), 512, GEMM_SMEM>>>(
        hid_h, wqkvt_hi, wqkvt_lo, mixed_raw, BL, CONV_DIM, DD, INV_WSCALE);
    // ---- GEMM2 (1-term): z = hidden @ W_z ----
    gemm_hmma_kernel<1><<<dim3(VAL_DIM / 128, BL / 256), 512, GEMM_SMEM>>>(
        hid_h, wzt_hi, wzt_lo, zbuf, BL, VAL_DIM, DD, INV_WSCALE);

    // ---- beta / decay ----
    ba_kernel<<<BL, 128>>>(hidden, W_b, W_a, dt_bias, A_log, betab, decb);
    // ---- tiled conv+silu+l2norm for q,k ----
    convqk_kernel<<<dim3(BL / CTL, HK), 256>>>(mixed_raw, conv_w, qn, kn);
    // ---- tiled conv+silu for v ----
    convv_kernel<<<dim3(BL / CTL, VAL_DIM / 256), 256>>>(mixed_raw, conv_w, vconv);
    // ---- gated delta-rule recurrence ----
    delta_kernel<<<BB * HV * 2, 256>>>(qn, kn, vconv, betab, decb, core);
    // ---- gated RMSNorm -> fp16 ----
    gatednorm_kernel<<<BL * HV, 128>>>(zbuf, norm_w, core, gh);

    // ---- GEMM3 (1-term): out = gated @ W_out ----
    gemm_hmma_kernel<1><<<dim3(DD / 128, BL / 256), 512, GEMM_SMEM>>>(
        gh, woutt_hi, woutt_lo, out, BL, DD, VAL_DIM, INV_WSCALE);
}

// round 14
// speedup vs baseline: 1.5634x; 1.5634x over previous
#include <cuda_runtime.h>
#include <cuda_fp16.h>
#include <math.h>
#include <cstdint>

// ---------------- problem constants ----------------
#define BB 2
#define LL 2048
#define DD 2048
#define HV 32
#define HK 16
#define DK 128
#define DV 128
#define KCONV 4
#define KEY_DIM 2048
#define VAL_DIM 4096
#define CONV_DIM 8192
#define BL (BB * LL)          // 4096 rows
#define WSCALE 64.0f
#define INV_WSCALE (1.0f / 64.0f)

// ---------------- scratch (static device globals) ----------------
__device__ float g_mixed_raw[(size_t)BL * CONV_DIM];      // GEMM1 out
__device__ float g_vconv[(size_t)BL * VAL_DIM];           // conv+silu of v part
__device__ float g_z[(size_t)BL * VAL_DIM];
__device__ float g_qn[(size_t)BL * HK * DK];
__device__ float g_kn[(size_t)BL * HK * DK];
__device__ float g_beta[(size_t)BL * HV];
__device__ float g_dec[(size_t)BL * HV];
__device__ float g_core[(size_t)BL * HV * DV];
// fp16 operands
__device__ __half g_hid_h[(size_t)BL * DD];
__device__ __half g_wqkvt_hi[(size_t)CONV_DIM * DD];
__device__ __half g_wqkvt_lo[(size_t)CONV_DIM * DD];
__device__ __half g_wzt_hi[(size_t)VAL_DIM * DD];
__device__ __half g_wzt_lo[(size_t)VAL_DIM * DD];
__device__ __half g_woutt_hi[(size_t)DD * VAL_DIM];
__device__ __half g_woutt_lo[(size_t)DD * VAL_DIM];
__device__ __half g_gh[(size_t)BL * VAL_DIM];

// ============================================================================
// PTX helpers (legal on plain sm_103 target)
// ============================================================================
__device__ __forceinline__ uint32_t smem_u32(const void* p) {
    uint32_t a;
    asm("{ .reg .u64 t; cvta.to.shared.u64 t, %1; cvt.u32.u64 %0, t; }"
        : "=r"(a) : "l"(p));
    return a;
}
__device__ __forceinline__ void cp_async16(uint32_t dst, const void* src) {
    asm volatile("cp.async.cg.shared.global [%0], [%1], 16;" :: "r"(dst), "l"(src));
}
__device__ __forceinline__ void cp_async4(uint32_t dst, const void* src) {
    asm volatile("cp.async.ca.shared.global [%0], [%1], 4;" :: "r"(dst), "l"(src));
}
#define CP_COMMIT() asm volatile("cp.async.commit_group;" ::: "memory")
#define CP_WAIT2()  asm volatile("cp.async.wait_group 2;" ::: "memory")
#define CP_WAIT3()  asm volatile("cp.async.wait_group 3;" ::: "memory")

__device__ __forceinline__ void ldmx4(uint32_t* r, uint32_t addr) {
    asm volatile("ldmatrix.sync.aligned.m8n8.x4.shared.b16 {%0,%1,%2,%3}, [%4];"
                 : "=r"(r[0]), "=r"(r[1]), "=r"(r[2]), "=r"(r[3]) : "r"(addr));
}
__device__ __forceinline__ void mma16816h(float* c, const uint32_t* a, const uint32_t* b) {
    asm volatile(
        "mma.sync.aligned.m16n8k16.row.col.f32.f16.f16.f32 "
        "{%0,%1,%2,%3}, {%4,%5,%6,%7}, {%8,%9}, {%0,%1,%2,%3};"
        : "+f"(c[0]), "+f"(c[1]), "+f"(c[2]), "+f"(c[3])
        : "r"(a[0]), "r"(a[1]), "r"(a[2]), "r"(a[3]), "r"(b[0]), "r"(b[1]));
}

// packed fp32x2 ops (FFMA2)
typedef unsigned long long ull;
__device__ __forceinline__ ull pk2(float lo, float hi) {
    ull r; asm("mov.b64 %0, {%1, %2};" : "=l"(r) : "f"(lo), "f"(hi)); return r;
}
__device__ __forceinline__ float2 upk2(ull v) {
    float2 f; asm("mov.b64 {%0, %1}, %2;" : "=f"(f.x), "=f"(f.y) : "l"(v)); return f;
}
__device__ __forceinline__ ull fma2_(ull a, ull b, ull c) {
    ull d; asm("fma.rn.f32x2 %0, %1, %2, %3;" : "=l"(d) : "l"(a), "l"(b), "l"(c)); return d;
}
__device__ __forceinline__ ull mul2_(ull a, ull b) {
    ull d; asm("mul.rn.f32x2 %0, %1, %2;" : "=l"(d) : "l"(a), "l"(b)); return d;
}

// ============================================================================
// prep: fp32 -> fp16 (A operand)
// ============================================================================
__global__ __launch_bounds__(256) void cvt16_kernel(
    const float* __restrict__ x, __half* __restrict__ out, size_t n4)
{
    size_t i = (size_t)blockIdx.x * blockDim.x + threadIdx.x;
    if (i >= n4) return;
    float4 v = reinterpret_cast<const float4*>(x)[i];
    __half2 h0 = __floats2half2_rn(v.x, v.y);
    __half2 h1 = __floats2half2_rn(v.z, v.w);
    reinterpret_cast<__half2*>(out)[i * 2 + 0] = h0;
    reinterpret_cast<__half2*>(out)[i * 2 + 1] = h1;
}

// ============================================================================
// prep: W[Kdim,Ndim] fp32 -> (W*64)^T hi/lo fp16 [Ndim,Kdim]
// ============================================================================
__global__ __launch_bounds__(256) void transpose_split_kernel(
    const float* __restrict__ W, __half* __restrict__ Thi,
    __half* __restrict__ Tlo, int Kdim, int Ndim)
{
    __shared__ float s[32][33];
    const int n0 = blockIdx.x * 32;
    const int k0 = blockIdx.y * 32;
    const int tx = threadIdx.x & 31;
    const int ty = threadIdx.x >> 5;
#pragma unroll
    for (int r = ty; r < 32; r += 8)
        s[r][tx] = W[(size_t)(k0 + r) * Ndim + n0 + tx];
    __syncthreads();
#pragma unroll
    for (int r = ty; r < 32; r += 8) {
        float x = s[tx][r] * WSCALE;
        __half h = __float2half_rn(x);
        Thi[(size_t)(n0 + r) * Kdim + k0 + tx] = h;
        Tlo[(size_t)(n0 + r) * Kdim + k0 + tx] = __float2half_rn(x - __half2float(h));
    }
}

// ============================================================================
// HMMA fp16 GEMM: C[M,N] = outscale * A[M,K] @ (Bhi [+ Blo])[N,K]^T
// TERMS=2: hi+lo compensated weights (GEMM1). TERMS=1: hi only (GEMM2/3).
// Block 256x128, BK=32, 16 warps (4m x 4n), warp tile 64x32,
// cp.async 4-stage pipeline, ldmatrix from 80B-padded smem rows.
// ============================================================================
#define GBK 32
#define ROWB 80
#define A_BYTES (256 * ROWB)
#define B_BYTES (128 * ROWB)
#define STAGE_BYTES (A_BYTES + 2 * B_BYTES)        // 40960
#define NSTAGE 4
#define GEMM_SMEM (NSTAGE * STAGE_BYTES)           // 163840

template<int TERMS>
__global__ void __launch_bounds__(512, 1) gemm_hmma_kernel(
    const __half* __restrict__ A,
    const __half* __restrict__ Bhi, const __half* __restrict__ Blo,
    float* __restrict__ C, int M, int N, int K, float outscale)
{
    extern __shared__ char smem[];
    const uint32_t sb = smem_u32(smem);
    const int tid  = threadIdx.x;
    const int wid  = tid >> 5;
    const int lane = tid & 31;
    const int warp_m = wid & 3;
    const int warp_n = wid >> 2;
    const int m0 = blockIdx.y * 256;
    const int n0 = blockIdx.x * 128;

    const __half* asrc  = A   + (size_t)m0 * K;
    const __half* bsrc[2] = { Bhi + (size_t)n0 * K,
                              (TERMS == 2) ? Blo + (size_t)n0 * K : Bhi + (size_t)n0 * K };

    const int NCHUNK = (TERMS == 2) ? 2048 : 1536;   // 16B chunks per stage

    auto load_stage = [&](int buf, int k0) {
        const uint32_t base = sb + buf * STAGE_BYTES;
#pragma unroll
        for (int i = 0; i < (TERMS == 2 ? 4 : 3); i++) {
            int c = tid + i * 512;
            if (c >= NCHUNK) break;
            if (c < 1024) {
                int row = c >> 2, col = c & 3;
                cp_async16(base + row * ROWB + col * 16,
                           asrc + (size_t)row * K + k0 + col * 8);
            } else {
                int d = c - 1024;
                int arr = d >> 9;
                int w = d & 511;
                int row = w >> 2, col = w & 3;
                cp_async16(base + A_BYTES + arr * B_BYTES + row * ROWB + col * 16,
                           bsrc[arr] + (size_t)row * K + k0 + col * 8);
            }
        }
    };

    float acc[4][4][4];
#pragma unroll
    for (int a = 0; a < 4; a++)
#pragma unroll
        for (int b = 0; b < 4; b++)
#pragma unroll
            for (int cc = 0; cc < 4; cc++) acc[a][b][cc] = 0.f;

    const int NIT = K / GBK;
    load_stage(0, 0);       CP_COMMIT();
    load_stage(1, GBK);     CP_COMMIT();
    load_stage(2, 2 * GBK); CP_COMMIT();

    const int a_row_l = (lane & 15);
    const int a_kadd  = (lane >> 4) << 3;
    const int b_nadd  = (lane & 7) + ((lane >> 4) << 3);
    const int b_kadd  = ((lane >> 3) & 1) << 3;

    for (int it = 0; it < NIT; ++it) {
        CP_WAIT2();
        __syncthreads();
        if (it + 3 < NIT) load_stage((it + 3) & (NSTAGE - 1), (it + 3) * GBK);
        CP_COMMIT();

        const uint32_t stg  = sb + (it & (NSTAGE - 1)) * STAGE_BYTES;
        const uint32_t ab   = stg;
        const uint32_t bhib = stg + A_BYTES;
        const uint32_t blob = stg + A_BYTES + B_BYTES;

#pragma unroll
        for (int ks = 0; ks < 2; ks++) {
            const int k0 = ks * 16;
            uint32_t ahf[4][4];
            const uint32_t aoff = (uint32_t)((warp_m * 64 + a_row_l) * ROWB + (k0 + a_kadd) * 2);
#pragma unroll
            for (int mt = 0; mt < 4; mt++)
                ldmx4(ahf[mt], ab + aoff + mt * 16 * ROWB);

            uint32_t bhf[2][4], blf[2][4];
            const uint32_t boff = (uint32_t)((warp_n * 32 + b_nadd) * ROWB + (k0 + b_kadd) * 2);
#pragma unroll
            for (int bt = 0; bt < 2; bt++) {
                ldmx4(bhf[bt], bhib + boff + bt * 16 * ROWB);
                if (TERMS == 2) ldmx4(blf[bt], blob + boff + bt * 16 * ROWB);
            }
#pragma unroll
            for (int mt = 0; mt < 4; mt++) {
#pragma unroll
                for (int nt = 0; nt < 4; nt++) {
                    const uint32_t* bh = &bhf[nt >> 1][(nt & 1) * 2];
                    float* c = acc[mt][nt];
                    mma16816h(c, ahf[mt], bh);
                    if (TERMS == 2) {
                        const uint32_t* bl = &blf[nt >> 1][(nt & 1) * 2];
                        mma16816h(c, ahf[mt], bl);
                    }
                }
            }
        }
    }

    const int mrow = lane >> 2;
    const int ncol = (lane & 3) * 2;
#pragma unroll
    for (int mt = 0; mt < 4; mt++) {
#pragma unroll
        for (int nt = 0; nt < 4; nt++) {
            const int m = m0 + warp_m * 64 + mt * 16 + mrow;
            const int n = n0 + warp_n * 32 + nt * 8 + ncol;
            *reinterpret_cast<float2*>(C + (size_t)m * N + n) =
                make_float2(acc[mt][nt][0] * outscale, acc[mt][nt][1] * outscale);
            *reinterpret_cast<float2*>(C + (size_t)(m + 8) * N + n) =
                make_float2(acc[mt][nt][2] * outscale, acc[mt][nt][3] * outscale);
        }
    }
}

// ============================================================================
// b/a projection + beta/decay — R9 version (known-good)
// ============================================================================
__global__ __launch_bounds__(128) void ba_kernel(
    const float* __restrict__ hidden,
    const float* __restrict__ Wb, const float* __restrict__ Wa,
    const float* __restrict__ dt_bias, const float* __restrict__ A_log,
    float* __restrict__ beta, float* __restrict__ dec)
{
    __shared__ float h_sh[DD];
    __shared__ float partial[128];
    const size_t bl = blockIdx.x;
    const int t = threadIdx.x;
    const float* hrow = hidden + bl * DD;
    for (int i = t; i < DD; i += 128) h_sh[i] = hrow[i];
    __syncthreads();

    const int col  = t & 63;
    const int part = t >> 6;
    const float* W = (col < 32) ? Wb : Wa;
    const int cc = col & 31;
    float acc = 0.f;
    const int d0 = part * (DD / 2);
#pragma unroll 8
    for (int d = d0; d < d0 + DD / 2; d++) acc = fmaf(h_sh[d], W[d * HV + cc], acc);
    partial[t] = acc;
    __syncthreads();
    if (t < 64) {
        float v = partial[t] + partial[t + 64];
        if (col < 32) {
            beta[bl * HV + cc] = 1.f / (1.f + expf(-v));
        } else {
            float x = v + dt_bias[cc];
            float sp = (x > 20.f) ? x : log1pf(expf(x));
            dec[bl * HV + cc] = expf(-expf(A_log[cc]) * sp);
        }
    }
}

// ============================================================================
// Tiled conv+SiLU+l2norm for q,k — 8 l's per block (known-good R12)
// ============================================================================
#define CTL 8
__global__ __launch_bounds__(256) void convqk_kernel(
    const float* __restrict__ raw, const float* __restrict__ w,
    float* __restrict__ qn, float* __restrict__ kn)
{
    __shared__ float taps[CTL + 3][256];
    __shared__ float red[CTL][8];

    const int tile = blockIdx.x;
    const int hk   = blockIdx.y;
    const int b    = tile / (LL / CTL);
    const int l0   = (tile % (LL / CTL)) * CTL;
    const int t = threadIdx.x;
    const bool isk = t >= 128;
    const int d = t & 127;
    const int wid = t >> 5;
    const int ch = (isk ? KEY_DIM : 0) + hk * DK + d;

    for (int i = t; i < (CTL + 3) * 256; i += 256) {
        const int r = i >> 8;
        const int c = i & 255;
        const int gl = l0 + r - 3;
        const int cch = ((c < 128) ? 0 : KEY_DIM) + hk * DK + (c & 127);
        taps[r][c] = (gl >= 0)
            ? raw[((size_t)b * LL + gl) * CONV_DIM + cch] : 0.f;
    }
    __syncthreads();

    const float4 wv = reinterpret_cast<const float4*>(w)[ch];
    float xr[CTL];
#pragma unroll
    for (int l = 0; l < CTL; l++) {
        float acc = taps[l + 3][t] * wv.w;
        acc = fmaf(taps[l + 2][t], wv.z, acc);
        acc = fmaf(taps[l + 1][t], wv.y, acc);
        acc = fmaf(taps[l + 0][t], wv.x, acc);
        xr[l] = acc / (1.f + expf(-acc));
        float ss = xr[l] * xr[l];
#pragma unroll
        for (int o = 16; o > 0; o >>= 1) ss += __shfl_down_sync(0xffffffffu, ss, o);
        if ((t & 31) == 0) red[l][wid] = ss;
    }
    __syncthreads();

#pragma unroll
    for (int l = 0; l < CTL; l++) {
        float tot = isk ? (red[l][4] + red[l][5] + red[l][6] + red[l][7])
                        : (red[l][0] + red[l][1] + red[l][2] + red[l][3]);
        float inv = rsqrtf(tot + 1e-6f);
        if (!isk) inv *= 0.08838834764831845f;
        const size_t orow = ((size_t)b * LL + l0 + l) * HK + hk;
        (isk ? kn : qn)[orow * DK + d] = xr[l] * inv;
    }
}

// ============================================================================
// Tiled conv+SiLU for v -> compact [BL, VAL_DIM] (known-good R12)
// ============================================================================
__global__ __launch_bounds__(256) void convv_kernel(
    const float* __restrict__ raw, const float* __restrict__ w,
    float* __restrict__ vconv)
{
    __shared__ float taps[CTL + 3][256];

    const int tile = blockIdx.x;
    const int cb   = blockIdx.y;
    const int b    = tile / (LL / CTL);
    const int l0   = (tile % (LL / CTL)) * CTL;
    const int t = threadIdx.x;
    const int ch = 2 * KEY_DIM + cb * 256 + t;
    const int vch = cb * 256 + t;

    for (int i = t; i < (CTL + 3) * 256; i += 256) {
        const int r = i >> 8;
        const int c = i & 255;
        const int gl = l0 + r - 3;
        taps[r][c] = (gl >= 0)
            ? raw[((size_t)b * LL + gl) * CONV_DIM + 2 * KEY_DIM + cb * 256 + c] : 0.f;
    }
    __syncthreads();

    const float4 wv = reinterpret_cast<const float4*>(w)[ch];
#pragma unroll
    for (int l = 0; l < CTL; l++) {
        float acc = taps[l + 3][t] * wv.w;
        acc = fmaf(taps[l + 2][t], wv.z, acc);
        acc = fmaf(taps[l + 1][t], wv.y, acc);
        acc = fmaf(taps[l + 0][t], wv.x, acc);
        vconv[((size_t)b * LL + l0 + l) * VAL_DIM + vch] =
            acc / (1.f + expf(-acc));
    }
}

// ============================================================================
// Gated delta-rule recurrence — R9 version (known-good)
// ============================================================================
#define DNBUF 4
__global__ __launch_bounds__(256) void delta_kernel(
    const float* __restrict__ qn, const float* __restrict__ kn,
    const float* __restrict__ vconv,
    const float* __restrict__ beta, const float* __restrict__ dec,
    float* __restrict__ core)
{
    const int c = blockIdx.x;
    const int b  = c >> 6;
    const int rm = c & 63;
    const int h  = rm >> 1;
    const int vh = rm & 1;
    const int hk = h >> 1;
    const int tid = threadIdx.x;
    const int vl = tid & 63;
    const int kh = tid >> 6;
    const int v  = vh * 64 + vl;

    __shared__ float ksh[DNBUF][128], qsh[DNBUF][128], vsh[DNBUF][64];
    __shared__ float scl[DNBUF][2];
    __shared__ float kvp[256], op[256];

    const uint32_t ksh_a = smem_u32(&ksh[0][0]);
    const uint32_t qsh_a = smem_u32(&qsh[0][0]);
    const uint32_t vsh_a = smem_u32(&vsh[0][0]);
    const uint32_t scl_a = smem_u32(&scl[0][0]);

    auto issue = [&](int l) {
        const int s = l & (DNBUF - 1);
        const size_t base = (size_t)b * LL + l;
        if (tid < 128)
            cp_async4(ksh_a + (s * 128 + tid) * 4,
                      kn + (base * HK + hk) * DK + tid);
        else
            cp_async4(qsh_a + (s * 128 + tid - 128) * 4,
                      qn + (base * HK + hk) * DK + (tid - 128));
        if (tid < 64)
            cp_async4(vsh_a + (s * 64 + tid) * 4,
                      vconv + base * VAL_DIM + (size_t)h * DV + vh * 64 + tid);
        else if (tid == 64)
            cp_async4(scl_a + (s * 2 + 0) * 4, dec + base * HV + h);
        else if (tid == 65)
            cp_async4(scl_a + (s * 2 + 1) * 4, beta + base * HV + h);
    };

    ull s2[16];
#pragma unroll
    for (int i = 0; i < 16; i++) s2[i] = 0ull;

    issue(0); CP_COMMIT();
    issue(1); CP_COMMIT();
    issue(2); CP_COMMIT();

    for (int l = 0; l < LL; l++) {
        const int s = l & (DNBUF - 1);
        if (l + 3 < LL) issue(l + 3);
        CP_COMMIT();
        CP_WAIT3();
        __syncthreads();

        const float dc = scl[s][0];
        const float bt = scl[s][1];
        const float2* kb2 = reinterpret_cast<const float2*>(&ksh[s][kh * 32]);
        const float2* qb2 = reinterpret_cast<const float2*>(&qsh[s][kh * 32]);

        const ull dc2 = pk2(dc, dc);
        ull kp[16];
        ull kv2 = 0ull;
#pragma unroll
        for (int j = 0; j < 16; j++) {
            float2 kf = kb2[j];
            kp[j] = pk2(kf.x, kf.y);
            s2[j] = mul2_(s2[j], dc2);
            kv2 = fma2_(kp[j], s2[j], kv2);
        }
        float2 kvf = upk2(kv2);
        kvp[kh * 64 + vl] = kvf.x + kvf.y;
        __syncthreads();

        const float kvs = kvp[vl] + kvp[64 + vl] + kvp[128 + vl] + kvp[192 + vl];
        const float delta = (vsh[s][vl] - kvs) * bt;
        const ull d2 = pk2(delta, delta);
        ull o2 = 0ull;
#pragma unroll
        for (int j = 0; j < 16; j++) {
            s2[j] = fma2_(kp[j], d2, s2[j]);
            float2 qf = qb2[j];
            o2 = fma2_(pk2(qf.x, qf.y), s2[j], o2);
        }
        float2 of = upk2(o2);
        op[kh * 64 + vl] = of.x + of.y;
        __syncthreads();

        if (kh == 0)
            core[((size_t)(b * LL + l) * HV + h) * DV + v] =
                op[vl] + op[64 + vl] + op[128 + vl] + op[192 + vl];
    }
}

// ============================================================================
// Gated RMSNorm -> fp16 (GEMM3 A operand)
// ============================================================================
__global__ __launch_bounds__(128) void gatednorm_kernel(
    const float* __restrict__ z, const float* __restrict__ norm_w,
    const float* __restrict__ core, __half* __restrict__ gh)
{
    const size_t row = blockIdx.x;
    const int t = threadIdx.x;
    const float zz = z[row * DV + t];
    const float cval = core[row * DV + t];
    const float g = cval * (zz / (1.f + expf(-zz)));

    __shared__ float red[4];
    float ss = g * g;
#pragma unroll
    for (int o = 16; o > 0; o >>= 1) ss += __shfl_down_sync(0xffffffffu, ss, o);
    if ((t & 31) == 0) red[t >> 5] = ss;
    __syncthreads();
    const float tot = red[0] + red[1] + red[2] + red[3];
    const float inv = rsqrtf(tot * (1.f / DV) + 1e-6f);
    gh[row * DV + t] = __float2half_rn(g * inv * norm_w[t]);
}

// ============================================================================
// launch
// ============================================================================
extern "C" void kernel_launch(void* const* d_in, const int* in_sizes, int n_in,
                              void* d_out, int out_size)
{
    const float* hidden  = (const float*)d_in[0];
    const float* W_qkv   = (const float*)d_in[1];
    const float* W_z     = (const float*)d_in[2];
    const float* W_b     = (const float*)d_in[3];
    const float* W_a     = (const float*)d_in[4];
    const float* conv_w  = (const float*)d_in[5];
    const float* dt_bias = (const float*)d_in[6];
    const float* A_log   = (const float*)d_in[7];
    const float* norm_w  = (const float*)d_in[8];
    const float* W_out   = (const float*)d_in[9];
    float* out = (float*)d_out;

    float *mixed_raw, *vconv, *zbuf, *qn, *kn, *betab, *decb, *core;
    __half *hid_h, *wqkvt_hi, *wqkvt_lo, *wzt_hi, *wzt_lo, *woutt_hi, *woutt_lo, *gh;
    cudaGetSymbolAddress((void**)&mixed_raw, g_mixed_raw);
    cudaGetSymbolAddress((void**)&vconv,     g_vconv);
    cudaGetSymbolAddress((void**)&zbuf,      g_z);
    cudaGetSymbolAddress((void**)&qn,        g_qn);
    cudaGetSymbolAddress((void**)&kn,        g_kn);
    cudaGetSymbolAddress((void**)&betab,     g_beta);
    cudaGetSymbolAddress((void**)&decb,      g_dec);
    cudaGetSymbolAddress((void**)&core,      g_core);
    cudaGetSymbolAddress((void**)&hid_h,     g_hid_h);
    cudaGetSymbolAddress((void**)&wqkvt_hi,  g_wqkvt_hi);
    cudaGetSymbolAddress((void**)&wqkvt_lo,  g_wqkvt_lo);
    cudaGetSymbolAddress((void**)&wzt_hi,    g_wzt_hi);
    cudaGetSymbolAddress((void**)&wzt_lo,    g_wzt_lo);
    cudaGetSymbolAddress((void**)&woutt_hi,  g_woutt_hi);
    cudaGetSymbolAddress((void**)&woutt_lo,  g_woutt_lo);
    cudaGetSymbolAddress((void**)&gh,        g_gh);

    cudaFuncSetAttribute(gemm_hmma_kernel<2>,
                         cudaFuncAttributeMaxDynamicSharedMemorySize, GEMM_SMEM);
    cudaFuncSetAttribute(gemm_hmma_kernel<1>,
                         cudaFuncAttributeMaxDynamicSharedMemorySize, GEMM_SMEM);

    // ---- prep ----
    cvt16_kernel<<<(unsigned)(((size_t)BL * DD / 4 + 255) / 256), 256>>>(
        hidden, hid_h, (size_t)BL * DD / 4);
    transpose_split_kernel<<<dim3(CONV_DIM / 32, DD / 32), 256>>>(
        W_qkv, wqkvt_hi, wqkvt_lo, DD, CONV_DIM);
    transpose_split_kernel<<<dim3(VAL_DIM / 32, DD / 32), 256>>>(
        W_z, wzt_hi, wzt_lo, DD, VAL_DIM);
    transpose_split_kernel<<<dim3(DD / 32, VAL_DIM / 32), 256>>>(
        W_out, woutt_hi, woutt_lo, VAL_DIM, DD);

    // ---- GEMM1 (2-term, feeds recurrence): mixed_raw = hidden @ W_qkv ----
    gemm_hmma_kernel<2><<<dim3(CONV_DIM / 128, BL / 256), 512, GEMM_SMEM>>>(
        hid_h, wqkvt_hi, wqkvt_lo, mixed_raw, BL, CONV_DIM, DD, INV_WSCALE);
    // ---- GEMM2 (1-term): z = hidden @ W_z ----
    gemm_hmma_kernel<1><<<dim3(VAL_DIM / 128, BL / 256), 512, GEMM_SMEM>>>(
        hid_h, wzt_hi, wzt_lo, zbuf, BL, VAL_DIM, DD, INV_WSCALE);

    // ---- beta / decay ----
    ba_kernel<<<BL, 128>>>(hidden, W_b, W_a, dt_bias, A_log, betab, decb);
    // ---- tiled conv+silu+l2norm for q,k ----
    convqk_kernel<<<dim3(BL / CTL, HK), 256>>>(mixed_raw, conv_w, qn, kn);
    // ---- tiled conv+silu for v ----
    convv_kernel<<<dim3(BL / CTL, VAL_DIM / 256), 256>>>(mixed_raw, conv_w, vconv);
    // ---- gated delta-rule recurrence ----
    delta_kernel<<<BB * HV * 2, 256>>>(qn, kn, vconv, betab, decb, core);
    // ---- gated RMSNorm -> fp16 ----
    gatednorm_kernel<<<BL * HV, 128>>>(zbuf, norm_w, core, gh);

    // ---- GEMM3 (1-term): out = gated @ W_out ----
    gemm_hmma_kernel<1><<<dim3(DD / 128, BL / 256), 512, GEMM_SMEM>>>(
        gh, woutt_hi, woutt_lo, out, BL, DD, VAL_DIM, INV_WSCALE);
}

// round 15
// speedup vs baseline: 1.7159x; 1.0976x over previous
#include <cuda_runtime.h>
#include <cuda_fp16.h>
#include <math.h>
#include <cstdint>

// ---------------- problem constants ----------------
#define BB 2
#define LL 2048
#define DD 2048
#define HV 32
#define HK 16
#define DK 128
#define DV 128
#define KCONV 4
#define KEY_DIM 2048
#define VAL_DIM 4096
#define CONV_DIM 8192
#define BL (BB * LL)          // 4096 rows
#define WSCALE 64.0f
#define INV_WSCALE (1.0f / 64.0f)

// ---------------- scratch (static device globals) ----------------
__device__ float g_mixed_raw[(size_t)BL * CONV_DIM];      // GEMM1 out
__device__ float g_vconv[(size_t)BL * VAL_DIM];           // conv+silu of v part
__device__ float g_z[(size_t)BL * VAL_DIM];
__device__ float g_qn[(size_t)BL * HK * DK];
__device__ float g_kn[(size_t)BL * HK * DK];
__device__ float g_beta[(size_t)BL * HV];
__device__ float g_dec[(size_t)BL * HV];
__device__ float g_core[(size_t)BL * HV * DV];
// fp16 operands
__device__ __half g_hid_h[(size_t)BL * DD];
__device__ __half g_wqkvt_hi[(size_t)CONV_DIM * DD];
__device__ __half g_wqkvt_lo[(size_t)CONV_DIM * DD];   // unused (1-term), kept for revert
__device__ __half g_wzt_hi[(size_t)VAL_DIM * DD];
__device__ __half g_wzt_lo[(size_t)VAL_DIM * DD];      // unused
__device__ __half g_woutt_hi[(size_t)DD * VAL_DIM];
__device__ __half g_woutt_lo[(size_t)DD * VAL_DIM];    // unused
__device__ __half g_gh[(size_t)BL * VAL_DIM];

// ============================================================================
// PTX helpers (legal on plain sm_103 target)
// ============================================================================
__device__ __forceinline__ uint32_t smem_u32(const void* p) {
    uint32_t a;
    asm("{ .reg .u64 t; cvta.to.shared.u64 t, %1; cvt.u32.u64 %0, t; }"
        : "=r"(a) : "l"(p));
    return a;
}
__device__ __forceinline__ void cp_async16(uint32_t dst, const void* src) {
    asm volatile("cp.async.cg.shared.global [%0], [%1], 16;" :: "r"(dst), "l"(src));
}
__device__ __forceinline__ void cp_async4(uint32_t dst, const void* src) {
    asm volatile("cp.async.ca.shared.global [%0], [%1], 4;" :: "r"(dst), "l"(src));
}
#define CP_COMMIT() asm volatile("cp.async.commit_group;" ::: "memory")
#define CP_WAIT2()  asm volatile("cp.async.wait_group 2;" ::: "memory")
#define CP_WAIT3()  asm volatile("cp.async.wait_group 3;" ::: "memory")

__device__ __forceinline__ void ldmx4(uint32_t* r, uint32_t addr) {
    asm volatile("ldmatrix.sync.aligned.m8n8.x4.shared.b16 {%0,%1,%2,%3}, [%4];"
                 : "=r"(r[0]), "=r"(r[1]), "=r"(r[2]), "=r"(r[3]) : "r"(addr));
}
__device__ __forceinline__ void mma16816h(float* c, const uint32_t* a, const uint32_t* b) {
    asm volatile(
        "mma.sync.aligned.m16n8k16.row.col.f32.f16.f16.f32 "
        "{%0,%1,%2,%3}, {%4,%5,%6,%7}, {%8,%9}, {%0,%1,%2,%3};"
        : "+f"(c[0]), "+f"(c[1]), "+f"(c[2]), "+f"(c[3])
        : "r"(a[0]), "r"(a[1]), "r"(a[2]), "r"(a[3]), "r"(b[0]), "r"(b[1]));
}

// packed fp32x2 ops (FFMA2)
typedef unsigned long long ull;
__device__ __forceinline__ ull pk2(float lo, float hi) {
    ull r; asm("mov.b64 %0, {%1, %2};" : "=l"(r) : "f"(lo), "f"(hi)); return r;
}
__device__ __forceinline__ float2 upk2(ull v) {
    float2 f; asm("mov.b64 {%0, %1}, %2;" : "=f"(f.x), "=f"(f.y) : "l"(v)); return f;
}
__device__ __forceinline__ ull fma2_(ull a, ull b, ull c) {
    ull d; asm("fma.rn.f32x2 %0, %1, %2, %3;" : "=l"(d) : "l"(a), "l"(b), "l"(c)); return d;
}
__device__ __forceinline__ ull mul2_(ull a, ull b) {
    ull d; asm("mul.rn.f32x2 %0, %1, %2;" : "=l"(d) : "l"(a), "l"(b)); return d;
}

// ============================================================================
// prep: fp32 -> fp16 (A operand)
// ============================================================================
__global__ __launch_bounds__(256) void cvt16_kernel(
    const float* __restrict__ x, __half* __restrict__ out, size_t n4)
{
    size_t i = (size_t)blockIdx.x * blockDim.x + threadIdx.x;
    if (i >= n4) return;
    float4 v = reinterpret_cast<const float4*>(x)[i];
    __half2 h0 = __floats2half2_rn(v.x, v.y);
    __half2 h1 = __floats2half2_rn(v.z, v.w);
    reinterpret_cast<__half2*>(out)[i * 2 + 0] = h0;
    reinterpret_cast<__half2*>(out)[i * 2 + 1] = h1;
}

// ============================================================================
// prep: W[Kdim,Ndim] fp32 -> (W*64)^T fp16 [Ndim,Kdim] (hi only; lo optional)
// ============================================================================
template<bool WRITE_LO>
__global__ __launch_bounds__(256) void transpose_split_kernel(
    const float* __restrict__ W, __half* __restrict__ Thi,
    __half* __restrict__ Tlo, int Kdim, int Ndim)
{
    __shared__ float s[32][33];
    const int n0 = blockIdx.x * 32;
    const int k0 = blockIdx.y * 32;
    const int tx = threadIdx.x & 31;
    const int ty = threadIdx.x >> 5;
#pragma unroll
    for (int r = ty; r < 32; r += 8)
        s[r][tx] = W[(size_t)(k0 + r) * Ndim + n0 + tx];
    __syncthreads();
#pragma unroll
    for (int r = ty; r < 32; r += 8) {
        float x = s[tx][r] * WSCALE;
        __half h = __float2half_rn(x);
        Thi[(size_t)(n0 + r) * Kdim + k0 + tx] = h;
        if (WRITE_LO)
            Tlo[(size_t)(n0 + r) * Kdim + k0 + tx] = __float2half_rn(x - __half2float(h));
    }
}

// ============================================================================
// HMMA fp16 GEMM: C[M,N] = outscale * A[M,K] @ (Bhi [+ Blo])[N,K]^T
// ============================================================================
#define GBK 32
#define ROWB 80
#define A_BYTES (256 * ROWB)
#define B_BYTES (128 * ROWB)
#define STAGE_BYTES (A_BYTES + 2 * B_BYTES)        // 40960
#define NSTAGE 4
#define GEMM_SMEM (NSTAGE * STAGE_BYTES)           // 163840

template<int TERMS>
__global__ void __launch_bounds__(512, 1) gemm_hmma_kernel(
    const __half* __restrict__ A,
    const __half* __restrict__ Bhi, const __half* __restrict__ Blo,
    float* __restrict__ C, int M, int N, int K, float outscale)
{
    extern __shared__ char smem[];
    const uint32_t sb = smem_u32(smem);
    const int tid  = threadIdx.x;
    const int wid  = tid >> 5;
    const int lane = tid & 31;
    const int warp_m = wid & 3;
    const int warp_n = wid >> 2;
    const int m0 = blockIdx.y * 256;
    const int n0 = blockIdx.x * 128;

    const __half* asrc  = A   + (size_t)m0 * K;
    const __half* bsrc[2] = { Bhi + (size_t)n0 * K,
                              (TERMS == 2) ? Blo + (size_t)n0 * K : Bhi + (size_t)n0 * K };

    const int NCHUNK = (TERMS == 2) ? 2048 : 1536;

    auto load_stage = [&](int buf, int k0) {
        const uint32_t base = sb + buf * STAGE_BYTES;
#pragma unroll
        for (int i = 0; i < (TERMS == 2 ? 4 : 3); i++) {
            int c = tid + i * 512;
            if (c >= NCHUNK) break;
            if (c < 1024) {
                int row = c >> 2, col = c & 3;
                cp_async16(base + row * ROWB + col * 16,
                           asrc + (size_t)row * K + k0 + col * 8);
            } else {
                int d = c - 1024;
                int arr = d >> 9;
                int w = d & 511;
                int row = w >> 2, col = w & 3;
                cp_async16(base + A_BYTES + arr * B_BYTES + row * ROWB + col * 16,
                           bsrc[arr] + (size_t)row * K + k0 + col * 8);
            }
        }
    };

    float acc[4][4][4];
#pragma unroll
    for (int a = 0; a < 4; a++)
#pragma unroll
        for (int b = 0; b < 4; b++)
#pragma unroll
            for (int cc = 0; cc < 4; cc++) acc[a][b][cc] = 0.f;

    const int NIT = K / GBK;
    load_stage(0, 0);       CP_COMMIT();
    load_stage(1, GBK);     CP_COMMIT();
    load_stage(2, 2 * GBK); CP_COMMIT();

    const int a_row_l = (lane & 15);
    const int a_kadd  = (lane >> 4) << 3;
    const int b_nadd  = (lane & 7) + ((lane >> 4) << 3);
    const int b_kadd  = ((lane >> 3) & 1) << 3;

    for (int it = 0; it < NIT; ++it) {
        CP_WAIT2();
        __syncthreads();
        if (it + 3 < NIT) load_stage((it + 3) & (NSTAGE - 1), (it + 3) * GBK);
        CP_COMMIT();

        const uint32_t stg  = sb + (it & (NSTAGE - 1)) * STAGE_BYTES;
        const uint32_t ab   = stg;
        const uint32_t bhib = stg + A_BYTES;
        const uint32_t blob = stg + A_BYTES + B_BYTES;

#pragma unroll
        for (int ks = 0; ks < 2; ks++) {
            const int k0 = ks * 16;
            uint32_t ahf[4][4];
            const uint32_t aoff = (uint32_t)((warp_m * 64 + a_row_l) * ROWB + (k0 + a_kadd) * 2);
#pragma unroll
            for (int mt = 0; mt < 4; mt++)
                ldmx4(ahf[mt], ab + aoff + mt * 16 * ROWB);

            uint32_t bhf[2][4], blf[2][4];
            const uint32_t boff = (uint32_t)((warp_n * 32 + b_nadd) * ROWB + (k0 + b_kadd) * 2);
#pragma unroll
            for (int bt = 0; bt < 2; bt++) {
                ldmx4(bhf[bt], bhib + boff + bt * 16 * ROWB);
                if (TERMS == 2) ldmx4(blf[bt], blob + boff + bt * 16 * ROWB);
            }
#pragma unroll
            for (int mt = 0; mt < 4; mt++) {
#pragma unroll
                for (int nt = 0; nt < 4; nt++) {
                    const uint32_t* bh = &bhf[nt >> 1][(nt & 1) * 2];
                    float* c = acc[mt][nt];
                    mma16816h(c, ahf[mt], bh);
                    if (TERMS == 2) {
                        const uint32_t* bl = &blf[nt >> 1][(nt & 1) * 2];
                        mma16816h(c, ahf[mt], bl);
                    }
                }
            }
        }
    }

    const int mrow = lane >> 2;
    const int ncol = (lane & 3) * 2;
#pragma unroll
    for (int mt = 0; mt < 4; mt++) {
#pragma unroll
        for (int nt = 0; nt < 4; nt++) {
            const int m = m0 + warp_m * 64 + mt * 16 + mrow;
            const int n = n0 + warp_n * 32 + nt * 8 + ncol;
            *reinterpret_cast<float2*>(C + (size_t)m * N + n) =
                make_float2(acc[mt][nt][0] * outscale, acc[mt][nt][1] * outscale);
            *reinterpret_cast<float2*>(C + (size_t)(m + 8) * N + n) =
                make_float2(acc[mt][nt][2] * outscale, acc[mt][nt][3] * outscale);
        }
    }
}

// ============================================================================
// b/a projection + beta/decay — tiled mini-GEMM (R10 version, retried alone).
// Block: 32 rows x 64 cols (cols 0..31 -> Wb, 32..63 -> Wa), 256 threads.
// ============================================================================
#define BA_ROWS 32
__global__ __launch_bounds__(256) void ba_kernel(
    const float* __restrict__ hidden,
    const float* __restrict__ Wb, const float* __restrict__ Wa,
    const float* __restrict__ dt_bias, const float* __restrict__ A_log,
    float* __restrict__ beta, float* __restrict__ dec)
{
    __shared__ float hs[BA_ROWS][65];
    __shared__ float ws[64][65];
    const int r0 = blockIdx.x * BA_ROWS;
    const int t = threadIdx.x;
    const int row  = t >> 3;          // 0..31
    const int colg = (t & 7) * 8;     // 0,8,...,56

    float acc[8];
#pragma unroll
    for (int j = 0; j < 8; j++) acc[j] = 0.f;

    for (int k0 = 0; k0 < DD; k0 += 64) {
#pragma unroll
        for (int i = t; i < BA_ROWS * 16; i += 256) {
            int r = i >> 4, c4 = (i & 15) * 4;
            float4 v = *reinterpret_cast<const float4*>(
                hidden + (size_t)(r0 + r) * DD + k0 + c4);
            hs[r][c4 + 0] = v.x; hs[r][c4 + 1] = v.y;
            hs[r][c4 + 2] = v.z; hs[r][c4 + 3] = v.w;
        }
#pragma unroll
        for (int i = t; i < 64 * 16; i += 256) {
            int kk = i >> 4, c4 = (i & 15) * 4;
            float4 v;
            if (c4 < 32)
                v = *reinterpret_cast<const float4*>(Wb + (size_t)(k0 + kk) * HV + c4);
            else
                v = *reinterpret_cast<const float4*>(Wa + (size_t)(k0 + kk) * HV + (c4 - 32));
            ws[kk][c4 + 0] = v.x; ws[kk][c4 + 1] = v.y;
            ws[kk][c4 + 2] = v.z; ws[kk][c4 + 3] = v.w;
        }
        __syncthreads();
#pragma unroll 8
        for (int kk = 0; kk < 64; kk++) {
            float h = hs[row][kk];
#pragma unroll
            for (int j = 0; j < 8; j++)
                acc[j] = fmaf(h, ws[kk][colg + j], acc[j]);
        }
        __syncthreads();
    }

    const size_t grow = r0 + row;
#pragma unroll
    for (int j = 0; j < 8; j++) {
        int col = colg + j;
        float v = acc[j];
        if (col < 32) {
            beta[grow * HV + col] = 1.f / (1.f + expf(-v));
        } else {
            int cc = col - 32;
            float x = v + dt_bias[cc];
            float sp = (x > 20.f) ? x : log1pf(expf(x));
            dec[grow * HV + cc] = expf(-expf(A_log[cc]) * sp);
        }
    }
}

// ============================================================================
// Tiled conv+SiLU+l2norm for q,k — 8 l's per block (known-good R12)
// ============================================================================
#define CTL 8
__global__ __launch_bounds__(256) void convqk_kernel(
    const float* __restrict__ raw, const float* __restrict__ w,
    float* __restrict__ qn, float* __restrict__ kn)
{
    __shared__ float taps[CTL + 3][256];
    __shared__ float red[CTL][8];

    const int tile = blockIdx.x;
    const int hk   = blockIdx.y;
    const int b    = tile / (LL / CTL);
    const int l0   = (tile % (LL / CTL)) * CTL;
    const int t = threadIdx.x;
    const bool isk = t >= 128;
    const int d = t & 127;
    const int wid = t >> 5;
    const int ch = (isk ? KEY_DIM : 0) + hk * DK + d;

    for (int i = t; i < (CTL + 3) * 256; i += 256) {
        const int r = i >> 8;
        const int c = i & 255;
        const int gl = l0 + r - 3;
        const int cch = ((c < 128) ? 0 : KEY_DIM) + hk * DK + (c & 127);
        taps[r][c] = (gl >= 0)
            ? raw[((size_t)b * LL + gl) * CONV_DIM + cch] : 0.f;
    }
    __syncthreads();

    const float4 wv = reinterpret_cast<const float4*>(w)[ch];
    float xr[CTL];
#pragma unroll
    for (int l = 0; l < CTL; l++) {
        float acc = taps[l + 3][t] * wv.w;
        acc = fmaf(taps[l + 2][t], wv.z, acc);
        acc = fmaf(taps[l + 1][t], wv.y, acc);
        acc = fmaf(taps[l + 0][t], wv.x, acc);
        xr[l] = acc / (1.f + expf(-acc));
        float ss = xr[l] * xr[l];
#pragma unroll
        for (int o = 16; o > 0; o >>= 1) ss += __shfl_down_sync(0xffffffffu, ss, o);
        if ((t & 31) == 0) red[l][wid] = ss;
    }
    __syncthreads();

#pragma unroll
    for (int l = 0; l < CTL; l++) {
        float tot = isk ? (red[l][4] + red[l][5] + red[l][6] + red[l][7])
                        : (red[l][0] + red[l][1] + red[l][2] + red[l][3]);
        float inv = rsqrtf(tot + 1e-6f);
        if (!isk) inv *= 0.08838834764831845f;
        const size_t orow = ((size_t)b * LL + l0 + l) * HK + hk;
        (isk ? kn : qn)[orow * DK + d] = xr[l] * inv;
    }
}

// ============================================================================
// Tiled conv+SiLU for v -> compact [BL, VAL_DIM] (known-good R12)
// ============================================================================
__global__ __launch_bounds__(256) void convv_kernel(
    const float* __restrict__ raw, const float* __restrict__ w,
    float* __restrict__ vconv)
{
    __shared__ float taps[CTL + 3][256];

    const int tile = blockIdx.x;
    const int cb   = blockIdx.y;
    const int b    = tile / (LL / CTL);
    const int l0   = (tile % (LL / CTL)) * CTL;
    const int t = threadIdx.x;
    const int ch = 2 * KEY_DIM + cb * 256 + t;
    const int vch = cb * 256 + t;

    for (int i = t; i < (CTL + 3) * 256; i += 256) {
        const int r = i >> 8;
        const int c = i & 255;
        const int gl = l0 + r - 3;
        taps[r][c] = (gl >= 0)
            ? raw[((size_t)b * LL + gl) * CONV_DIM + 2 * KEY_DIM + cb * 256 + c] : 0.f;
    }
    __syncthreads();

    const float4 wv = reinterpret_cast<const float4*>(w)[ch];
#pragma unroll
    for (int l = 0; l < CTL; l++) {
        float acc = taps[l + 3][t] * wv.w;
        acc = fmaf(taps[l + 2][t], wv.z, acc);
        acc = fmaf(taps[l + 1][t], wv.y, acc);
        acc = fmaf(taps[l + 0][t], wv.x, acc);
        vconv[((size_t)b * LL + l0 + l) * VAL_DIM + vch] =
            acc / (1.f + expf(-acc));
    }
}

// ============================================================================
// Gated delta-rule recurrence — R9 version (known-good)
// ============================================================================
#define DNBUF 4
__global__ __launch_bounds__(256) void delta_kernel(
    const float* __restrict__ qn, const float* __restrict__ kn,
    const float* __restrict__ vconv,
    const float* __restrict__ beta, const float* __restrict__ dec,
    float* __restrict__ core)
{
    const int c = blockIdx.x;
    const int b  = c >> 6;
    const int rm = c & 63;
    const int h  = rm >> 1;
    const int vh = rm & 1;
    const int hk = h >> 1;
    const int tid = threadIdx.x;
    const int vl = tid & 63;
    const int kh = tid >> 6;
    const int v  = vh * 64 + vl;

    __shared__ float ksh[DNBUF][128], qsh[DNBUF][128], vsh[DNBUF][64];
    __shared__ float scl[DNBUF][2];
    __shared__ float kvp[256], op[256];

    const uint32_t ksh_a = smem_u32(&ksh[0][0]);
    const uint32_t qsh_a = smem_u32(&qsh[0][0]);
    const uint32_t vsh_a = smem_u32(&vsh[0][0]);
    const uint32_t scl_a = smem_u32(&scl[0][0]);

    auto issue = [&](int l) {
        const int s = l & (DNBUF - 1);
        const size_t base = (size_t)b * LL + l;
        if (tid < 128)
            cp_async4(ksh_a + (s * 128 + tid) * 4,
                      kn + (base * HK + hk) * DK + tid);
        else
            cp_async4(qsh_a + (s * 128 + tid - 128) * 4,
                      qn + (base * HK + hk) * DK + (tid - 128));
        if (tid < 64)
            cp_async4(vsh_a + (s * 64 + tid) * 4,
                      vconv + base * VAL_DIM + (size_t)h * DV + vh * 64 + tid);
        else if (tid == 64)
            cp_async4(scl_a + (s * 2 + 0) * 4, dec + base * HV + h);
        else if (tid == 65)
            cp_async4(scl_a + (s * 2 + 1) * 4, beta + base * HV + h);
    };

    ull s2[16];
#pragma unroll
    for (int i = 0; i < 16; i++) s2[i] = 0ull;

    issue(0); CP_COMMIT();
    issue(1); CP_COMMIT();
    issue(2); CP_COMMIT();

    for (int l = 0; l < LL; l++) {
        const int s = l & (DNBUF - 1);
        if (l + 3 < LL) issue(l + 3);
        CP_COMMIT();
        CP_WAIT3();
        __syncthreads();

        const float dc = scl[s][0];
        const float bt = scl[s][1];
        const float2* kb2 = reinterpret_cast<const float2*>(&ksh[s][kh * 32]);
        const float2* qb2 = reinterpret_cast<const float2*>(&qsh[s][kh * 32]);

        const ull dc2 = pk2(dc, dc);
        ull kp[16];
        ull kv2 = 0ull;
#pragma unroll
        for (int j = 0; j < 16; j++) {
            float2 kf = kb2[j];
            kp[j] = pk2(kf.x, kf.y);
            s2[j] = mul2_(s2[j], dc2);
            kv2 = fma2_(kp[j], s2[j], kv2);
        }
        float2 kvf = upk2(kv2);
        kvp[kh * 64 + vl] = kvf.x + kvf.y;
        __syncthreads();

        const float kvs = kvp[vl] + kvp[64 + vl] + kvp[128 + vl] + kvp[192 + vl];
        const float delta = (vsh[s][vl] - kvs) * bt;
        const ull d2 = pk2(delta, delta);
        ull o2 = 0ull;
#pragma unroll
        for (int j = 0; j < 16; j++) {
            s2[j] = fma2_(kp[j], d2, s2[j]);
            float2 qf = qb2[j];
            o2 = fma2_(pk2(qf.x, qf.y), s2[j], o2);
        }
        float2 of = upk2(o2);
        op[kh * 64 + vl] = of.x + of.y;
        __syncthreads();

        if (kh == 0)
            core[((size_t)(b * LL + l) * HV + h) * DV + v] =
                op[vl] + op[64 + vl] + op[128 + vl] + op[192 + vl];
    }
}

// ============================================================================
// Gated RMSNorm -> fp16 (GEMM3 A operand)
// ============================================================================
__global__ __launch_bounds__(128) void gatednorm_kernel(
    const float* __restrict__ z, const float* __restrict__ norm_w,
    const float* __restrict__ core, __half* __restrict__ gh)
{
    const size_t row = blockIdx.x;
    const int t = threadIdx.x;
    const float zz = z[row * DV + t];
    const float cval = core[row * DV + t];
    const float g = cval * (zz / (1.f + expf(-zz)));

    __shared__ float red[4];
    float ss = g * g;
#pragma unroll
    for (int o = 16; o > 0; o >>= 1) ss += __shfl_down_sync(0xffffffffu, ss, o);
    if ((t & 31) == 0) red[t >> 5] = ss;
    __syncthreads();
    const float tot = red[0] + red[1] + red[2] + red[3];
    const float inv = rsqrtf(tot * (1.f / DV) + 1e-6f);
    gh[row * DV + t] = __float2half_rn(g * inv * norm_w[t]);
}

// ============================================================================
// launch
// ============================================================================
extern "C" void kernel_launch(void* const* d_in, const int* in_sizes, int n_in,
                              void* d_out, int out_size)
{
    const float* hidden  = (const float*)d_in[0];
    const float* W_qkv   = (const float*)d_in[1];
    const float* W_z     = (const float*)d_in[2];
    const float* W_b     = (const float*)d_in[3];
    const float* W_a     = (const float*)d_in[4];
    const float* conv_w  = (const float*)d_in[5];
    const float* dt_bias = (const float*)d_in[6];
    const float* A_log   = (const float*)d_in[7];
    const float* norm_w  = (const float*)d_in[8];
    const float* W_out   = (const float*)d_in[9];
    float* out = (float*)d_out;

    float *mixed_raw, *vconv, *zbuf, *qn, *kn, *betab, *decb, *core;
    __half *hid_h, *wqkvt_hi, *wqkvt_lo, *wzt_hi, *wzt_lo, *woutt_hi, *woutt_lo, *gh;
    cudaGetSymbolAddress((void**)&mixed_raw, g_mixed_raw);
    cudaGetSymbolAddress((void**)&vconv,     g_vconv);
    cudaGetSymbolAddress((void**)&zbuf,      g_z);
    cudaGetSymbolAddress((void**)&qn,        g_qn);
    cudaGetSymbolAddress((void**)&kn,        g_kn);
    cudaGetSymbolAddress((void**)&betab,     g_beta);
    cudaGetSymbolAddress((void**)&decb,      g_dec);
    cudaGetSymbolAddress((void**)&core,      g_core);
    cudaGetSymbolAddress((void**)&hid_h,     g_hid_h);
    cudaGetSymbolAddress((void**)&wqkvt_hi,  g_wqkvt_hi);
    cudaGetSymbolAddress((void**)&wqkvt_lo,  g_wqkvt_lo);
    cudaGetSymbolAddress((void**)&wzt_hi,    g_wzt_hi);
    cudaGetSymbolAddress((void**)&wzt_lo,    g_wzt_lo);
    cudaGetSymbolAddress((void**)&woutt_hi,  g_woutt_hi);
    cudaGetSymbolAddress((void**)&woutt_lo,  g_woutt_lo);
    cudaGetSymbolAddress((void**)&gh,        g_gh);

    cudaFuncSetAttribute(gemm_hmma_kernel<1>,
                         cudaFuncAttributeMaxDynamicSharedMemorySize, GEMM_SMEM);

    // ---- prep (hi-only weight transposes; lo path dead with 1-term GEMMs) ----
    cvt16_kernel<<<(unsigned)(((size_t)BL * DD / 4 + 255) / 256), 256>>>(
        hidden, hid_h, (size_t)BL * DD / 4);
    transpose_split_kernel<false><<<dim3(CONV_DIM / 32, DD / 32), 256>>>(
        W_qkv, wqkvt_hi, wqkvt_lo, DD, CONV_DIM);
    transpose_split_kernel<false><<<dim3(VAL_DIM / 32, DD / 32), 256>>>(
        W_z, wzt_hi, wzt_lo, DD, VAL_DIM);
    transpose_split_kernel<false><<<dim3(DD / 32, VAL_DIM / 32), 256>>>(
        W_out, woutt_hi, woutt_lo, VAL_DIM, DD);

    // ---- GEMM1 (1-term now): mixed_raw = hidden @ W_qkv ----
    gemm_hmma_kernel<1><<<dim3(CONV_DIM / 128, BL / 256), 512, GEMM_SMEM>>>(
        hid_h, wqkvt_hi, wqkvt_lo, mixed_raw, BL, CONV_DIM, DD, INV_WSCALE);
    // ---- GEMM2 (1-term): z = hidden @ W_z ----
    gemm_hmma_kernel<1><<<dim3(VAL_DIM / 128, BL / 256), 512, GEMM_SMEM>>>(
        hid_h, wzt_hi, wzt_lo, zbuf, BL, VAL_DIM, DD, INV_WSCALE);

    // ---- beta / decay (tiled mini-GEMM, isolated retry) ----
    ba_kernel<<<BL / BA_ROWS, 256>>>(hidden, W_b, W_a, dt_bias, A_log, betab, decb);
    // ---- tiled conv+silu+l2norm for q,k ----
    convqk_kernel<<<dim3(BL / CTL, HK), 256>>>(mixed_raw, conv_w, qn, kn);
    // ---- tiled conv+silu for v ----
    convv_kernel<<<dim3(BL / CTL, VAL_DIM / 256), 256>>>(mixed_raw, conv_w, vconv);
    // ---- gated delta-rule recurrence ----
    delta_kernel<<<BB * HV * 2, 256>>>(qn, kn, vconv, betab, decb, core);
    // ---- gated RMSNorm -> fp16 ----
    gatednorm_kernel<<<BL * HV, 128>>>(zbuf, norm_w, core, gh);

    // ---- GEMM3 (1-term): out = gated @ W_out ----
    gemm_hmma_kernel<1><<<dim3(DD / 128, BL / 256), 512, GEMM_SMEM>>>(
        gh, woutt_hi, woutt_lo, out, BL, DD, VAL_DIM, INV_WSCALE);
}